// round 5
// baseline (speedup 1.0000x reference)
#include <cuda_runtime.h>

#define EPSF 1e-20f

constexpr int B = 8, C = 32, O = 32, H = 256, W = 256;
constexpr int HW = H * W;
constexpr long long NTOT = (long long)B * O * HW;

constexpr int TILE = 16;        // spatial tile
constexpr int HALO = 20;        // TILE + 4
constexpr int THREADS = 512;

// smem layout (u64 units unless noted)
constexpr int HSTRIDE   = 401;                 // per-channel halo stride (odd -> conflict-free lane=c reads)
constexpr int SHALO_U64 = C * HSTRIDE;         // 12832 u64 = 102656 B (16B-aligned)
constexpr int SC_PAD    = 34;                  // per-pixel row stride (even -> 16B-aligned LDS.128)
constexpr int SC_OFF    = SHALO_U64;           // sC follows sHalo
constexpr int SC_U64    = 256 * SC_PAD;        // 8704 u64
constexpr int SW_OFF    = SC_OFF + SC_U64;     // sw2 copy
constexpr int SW_U64    = C * 25;              // 800 u64
constexpr int SMEM_BYTES = (SW_OFF + SW_U64) * 8;   // 178,688 B
// stage (floats) aliases sHalo region: 2 * 32 * 257 * 4 = 65,792 B <= 102,656 B
constexpr int STG_PAD = 257;

// K0 outputs
__device__ unsigned long long g_sw2[C * 25];
__device__ unsigned long long g_cwT2[C * O];   // [c][o], softplus'd, pair-packed
__device__ float g_wp[C];
__device__ float g_wp1inv[C];
__device__ float g_invSsw, g_invScw;

__device__ __forceinline__ float softplusf(float x) { return __logf(1.0f + __expf(x)); }

__device__ __forceinline__ unsigned long long pack2(float lo, float hi) {
    unsigned long long v;
    asm("mov.b64 %0, {%1, %2};" : "=l"(v) : "f"(lo), "f"(hi));
    return v;
}
__device__ __forceinline__ void unpack2(unsigned long long v, float& lo, float& hi) {
    asm("mov.b64 {%0, %1}, %2;" : "=f"(lo), "=f"(hi) : "l"(v));
}
__device__ __forceinline__ void fma2(unsigned long long& acc, unsigned long long a, unsigned long long w) {
    asm("fma.rn.f32x2 %0, %1, %2, %0;" : "+l"(acc) : "l"(a), "l"(w));
}

// ---------------------------------------------------------------------------
// K0: softplus all weights once; sums; transposed channel weights.
// ---------------------------------------------------------------------------
__global__ void k0_weights(const float* __restrict__ wprop,
                           const float* __restrict__ sw_raw,
                           const float* __restrict__ cw_raw) {
    __shared__ float red[256];
    int t = threadIdx.x;

    float s = 0.f;
    for (int i = t; i < C * 25; i += 256) {
        float w = softplusf(sw_raw[i]);
        g_sw2[i] = pack2(w, w);
        s += w;
    }
    red[t] = s; __syncthreads();
    for (int o = 128; o > 0; o >>= 1) { if (t < o) red[t] += red[t + o]; __syncthreads(); }
    if (t == 0) g_invSsw = 1.0f / red[0];
    __syncthreads();

    s = 0.f;
    for (int i = t; i < O * C; i += 256) {
        int c = i >> 5, o = i & 31;            // i = c*32 + o
        float w = softplusf(cw_raw[o * C + c]);
        g_cwT2[i] = pack2(w, w);
        s += w;
    }
    red[t] = s; __syncthreads();
    for (int o = 128; o > 0; o >>= 1) { if (t < o) red[t] += red[t + o]; __syncthreads(); }
    if (t == 0) g_invScw = 1.0f / red[0];

    if (t < C) {
        float wp = softplusf(wprop[t]);
        g_wp[t] = wp;
        g_wp1inv[t] = 1.0f / (wp + 1.0f);
    }
}

// ---------------------------------------------------------------------------
// Fused: prop -> depthwise 5x5 -> 1x1 channel conv -> outputs.
// One block per (b, 16x16 tile), all 32 channels in smem.
// ---------------------------------------------------------------------------
__global__ __launch_bounds__(THREADS, 1) void fused_kernel(
    const float* __restrict__ d, const float* __restrict__ cd,
    const float* __restrict__ gx, const float* __restrict__ cgx,
    const float* __restrict__ bias, float* __restrict__ out) {

    extern __shared__ char smem[];
    unsigned long long* sHalo = (unsigned long long*)smem;                 // [c][hh*20+ww], stride 401
    unsigned long long* sC    = (unsigned long long*)smem + SC_OFF;        // [pix][c], stride 34
    unsigned long long* sW    = (unsigned long long*)smem + SW_OFF;        // [c][25]
    float* stage = (float*)smem;                                           // [2][32][257], aliases sHalo

    const int tid = threadIdx.x;
    const int b = blockIdx.y;
    const int h0 = (blockIdx.x >> 4) * TILE;
    const int w0 = (blockIdx.x & 15) * TILE;

    // copy depthwise weights to smem
    for (int i = tid; i < C * 25; i += THREADS) sW[i] = g_sw2[i];

    // ---------------- Phase A: prop math into halo (12800 jobs) ----------------
    for (int j = 0; j < 25; j++) {
        int idx = tid + j * THREADS;          // 0 .. 12799
        int c = idx / 400;
        int rem = idx - c * 400;
        int hh = rem / HALO;
        int ww = rem - hh * HALO;
        int gh = h0 + hh - 2, gw = w0 + ww - 2;
        float p = 0.f, q = 0.f;
        if ((unsigned)gh < (unsigned)H && (unsigned)gw < (unsigned)W) {
            size_t g = ((size_t)b * C + c) * HW + (size_t)gh * W + gw;
            float dv = d[g], cdv = cd[g], gv = gx[g], cgv = cgx[g];
            float wp = g_wp[c];
            bool nl = (gw < W - 1), nf = (gw > 0);
            float dl = nl ? dv : 0.f, cl = nl ? cdv : 0.f;
            float dr = nf ? dv : 0.f, cr = nf ? cdv : 0.f;
            float cds = cl * cr;
            float height = __fdividef(cl * dl + cr * dr, cl + cr + EPSF);
            float gds = __fdividef((dr - dl) * 0.5f, height + EPSF);
            float t = wp * cgv;
            float gxp = __fdividef(t * gv + cds * gds, t + cds + EPSF);
            float cgp = (t + cds) * g_wp1inv[c];
            q = cgp;
            p = cgp * gxp;
        }
        sHalo[c * HSTRIDE + hh * HALO + ww] = pack2(p, q);
    }
    __syncthreads();

    // ---------------- Phase B: depthwise 5x5, thread = (c, row) ----------------
    {
        const int c = tid & 31;
        const int y = tid >> 5;               // 0..15
        const unsigned long long* hbase = sHalo + c * HSTRIDE;
        unsigned long long acc[TILE];
#pragma unroll
        for (int x = 0; x < TILE; x++) acc[x] = 0ULL;

#pragma unroll
        for (int i = 0; i < 5; i++) {
            unsigned long long row[HALO];
            const unsigned long long* rp = hbase + (y + i) * HALO;
#pragma unroll
            for (int k = 0; k < HALO; k++) row[k] = rp[k];
#pragma unroll
            for (int jj = 0; jj < 5; jj++) {
                unsigned long long w = sW[c * 25 + i * 5 + jj];
#pragma unroll
                for (int x = 0; x < TILE; x++) fma2(acc[x], row[x + jj], w);
            }
        }

        const float inv = g_invSsw;
#pragma unroll
        for (int x = 0; x < TILE; x++) {
            float n, dn; unpack2(acc[x], n, dn);
            float gxs = __fdividef(n, dn + EPSF);   // gx_s
            float qq  = dn * inv;                   // cgx_s
            sC[(y * TILE + x) * SC_PAD + c] = pack2(qq * gxs, qq);
        }
    }

    // preload channel-conv weights into registers (lane = output channel o)
    const int lane = tid & 31;
    const int warp = tid >> 5;
    unsigned long long wr[C];
#pragma unroll
    for (int cc = 0; cc < C; cc++) wr[cc] = g_cwT2[cc * O + lane];
    const float bs = bias[lane];
    const float invc = g_invScw;

    __syncthreads();   // sC complete; sHalo dead (stage may now be written)

    // ---------------- Phase C: 1x1 conv. warp w -> pixels 16w..16w+15, lane = o ----------------
    for (int px = 0; px < TILE; px++) {
        const int pix = warp * TILE + px;
        const unsigned long long* base = sC + pix * SC_PAD;
        unsigned long long acc0 = 0ULL, acc1 = 0ULL;
#pragma unroll
        for (int cc = 0; cc < C; cc += 2) {
            ulonglong2 a = *(const ulonglong2*)(base + cc);   // broadcast LDS.128
            fma2(acc0, a.x, wr[cc]);
            fma2(acc1, a.y, wr[cc + 1]);
        }
        float n0, d0, n1, d1;
        unpack2(acc0, n0, d0); unpack2(acc1, n1, d1);
        float n = n0 + n1, dn = d0 + d1;
        stage[lane * STG_PAD + pix]                 = __fdividef(n, dn + EPSF) + bs; // gx_out
        stage[O * STG_PAD + lane * STG_PAD + pix]   = dn * invc;                     // cgx_out
    }
    __syncthreads();

    // ---------------- Phase D: coalesced stores ----------------
    const size_t outb = (size_t)b * O * HW;
#pragma unroll
    for (int it = 0; it < 16; it++) {
        int idx = it * THREADS + tid;          // 0 .. 8191
        int o = idx >> 8;
        int pix = idx & 255;
        int py = pix >> 4, px = pix & 15;
        size_t g = outb + (size_t)o * HW + (size_t)(h0 + py) * W + (w0 + px);
        out[g]        = stage[o * STG_PAD + pix];
        out[NTOT + g] = stage[O * STG_PAD + o * STG_PAD + pix];
    }
}

// ---------------------------------------------------------------------------
extern "C" void kernel_launch(void* const* d_in, const int* in_sizes, int n_in,
                              void* d_out, int out_size) {
    const float* d     = (const float*)d_in[0];
    const float* cd    = (const float*)d_in[1];
    const float* gx    = (const float*)d_in[2];
    const float* cgx   = (const float*)d_in[3];
    const float* wprop = (const float*)d_in[4];
    const float* sw    = (const float*)d_in[5];
    const float* cw    = (const float*)d_in[6];
    const float* bias  = (const float*)d_in[7];
    float* out = (float*)d_out;

    cudaFuncSetAttribute(fused_kernel, cudaFuncAttributeMaxDynamicSharedMemorySize, SMEM_BYTES);

    k0_weights<<<1, 256>>>(wprop, sw, cw);

    dim3 grid(256, B);   // 16x16 tiles of 16x16 per batch
    fused_kernel<<<grid, THREADS, SMEM_BYTES>>>(d, cd, gx, cgx, bias, out);
}

// round 6
// speedup vs baseline: 1.4384x; 1.4384x over previous
#include <cuda_runtime.h>

#define EPSF 1e-20f

constexpr int B = 8, C = 32, O = 32, H = 256, W = 256;
constexpr int HW = H * W;                         // 65536
constexpr long long NTOT = (long long)B * O * HW; // per-tensor output elements

// Scratch (allocation-free rule: __device__ globals). 128 MiB.
__device__ float2 g_pq[B * C * HW];

// K0 outputs
__device__ unsigned long long g_sw2[C * 25];     // softplus(spatial_weight), pair-packed
__device__ unsigned long long g_cwT2[C * O];     // softplus(channel_weight) transposed [c][o], pair-packed
__device__ float g_wp[C];
__device__ float g_wp1inv[C];
__device__ float g_invSsw, g_invScw;

__device__ __forceinline__ float softplusf(float x) { return __logf(1.0f + __expf(x)); }

__device__ __forceinline__ unsigned long long pack2(float lo, float hi) {
    unsigned long long v;
    asm("mov.b64 %0, {%1, %2};" : "=l"(v) : "f"(lo), "f"(hi));
    return v;
}
__device__ __forceinline__ void unpack2(unsigned long long v, float& lo, float& hi) {
    asm("mov.b64 {%0, %1}, %2;" : "=f"(lo), "=f"(hi) : "l"(v));
}
__device__ __forceinline__ void fma2(unsigned long long& acc, unsigned long long a, unsigned long long w) {
    asm("fma.rn.f32x2 %0, %1, %2, %0;" : "+l"(acc) : "l"(a), "l"(w));
}

// ---------------------------------------------------------------------------
// K0: softplus all weights ONCE; sums; transposed channel weights.
// ---------------------------------------------------------------------------
__global__ void k0_weights(const float* __restrict__ wprop,
                           const float* __restrict__ sw_raw,
                           const float* __restrict__ cw_raw) {
    __shared__ float red[256];
    int t = threadIdx.x;

    float s = 0.f;
    for (int i = t; i < C * 25; i += 256) {
        float w = softplusf(sw_raw[i]);
        g_sw2[i] = pack2(w, w);
        s += w;
    }
    red[t] = s; __syncthreads();
    for (int o = 128; o > 0; o >>= 1) { if (t < o) red[t] += red[t + o]; __syncthreads(); }
    if (t == 0) g_invSsw = 1.0f / red[0];
    __syncthreads();

    s = 0.f;
    for (int i = t; i < O * C; i += 256) {
        int c = i >> 5, o = i & 31;            // i = c*32 + o
        float w = softplusf(cw_raw[o * C + c]);
        g_cwT2[i] = pack2(w, w);
        s += w;
    }
    red[t] = s; __syncthreads();
    for (int o = 128; o > 0; o >>= 1) { if (t < o) red[t] += red[t + o]; __syncthreads(); }
    if (t == 0) g_invScw = 1.0f / red[0];

    if (t < C) {
        float wp = softplusf(wprop[t]);
        g_wp[t] = wp;
        g_wp1inv[t] = 1.0f / (wp + 1.0f);
    }
}

// ---------------------------------------------------------------------------
// K12: fused elementwise-prop + depthwise 5x5 conv (pad=2), f32x2 packed.
// One block = one (b, c, 32x32 tile). No per-block weight reductions
// (reads K0's precomputed packed weights).
// ---------------------------------------------------------------------------
__global__ __launch_bounds__(256) void k12_prop_dwconv(
    const float* __restrict__ d, const float* __restrict__ cd,
    const float* __restrict__ gx, const float* __restrict__ cgx) {

    __shared__ unsigned long long sPQ[36 * 37];
    __shared__ unsigned long long sw2[25];

    const int tid = threadIdx.x;
    const int b = blockIdx.z, c = blockIdx.y;
    const int h0 = (blockIdx.x >> 3) * 32;
    const int w0 = (blockIdx.x & 7) * 32;

    if (tid < 25) sw2[tid] = g_sw2[c * 25 + tid];
    const float wp = g_wp[c];
    const float wp1inv = g_wp1inv[c];

    const size_t plane = ((size_t)b * C + c) * HW;

    // Phase A: halo tile (36x36) of per-pixel prop values, packed (p, q)
    for (int idx = tid; idx < 36 * 36; idx += 256) {
        int hh = idx / 36, ww = idx - hh * 36;
        int gh = h0 + hh - 2, gw = w0 + ww - 2;
        float p = 0.f, q = 0.f;
        if ((unsigned)gh < (unsigned)H && (unsigned)gw < (unsigned)W) {
            size_t g = plane + (size_t)gh * W + gw;
            float dv = d[g], cdv = cd[g], gv = gx[g], cgv = cgx[g];
            // reference slicing: *_left keeps value unless last col, *_right unless first col
            bool nl = (gw < W - 1), nf = (gw > 0);
            float dl = nl ? dv : 0.f, cl = nl ? cdv : 0.f;
            float dr = nf ? dv : 0.f, cr = nf ? cdv : 0.f;
            float cds = cl * cr;
            float height = __fdividef(cl * dl + cr * dr, cl + cr + EPSF);
            float gds = __fdividef((dr - dl) * 0.5f, height + EPSF);
            float t = wp * cgv;
            float gxp = __fdividef(t * gv + cds * gds, t + cds + EPSF);
            float cgp = (t + cds) * wp1inv;
            q = cgp;
            p = cgp * gxp;
        }
        sPQ[hh * 37 + ww] = pack2(p, q);
    }
    __syncthreads();

    // Phase B: conv. thread (tx, ty) -> col tx, rows ty*4 .. ty*4+3
    const int tx = tid & 31, ty = tid >> 5;
    const int r0 = ty * 4;
    unsigned long long acc[4] = {0ULL, 0ULL, 0ULL, 0ULL};

#pragma unroll
    for (int i = 0; i < 8; i++) {
        unsigned long long pv[5];
#pragma unroll
        for (int j = 0; j < 5; j++) pv[j] = sPQ[(r0 + i) * 37 + tx + j];
#pragma unroll
        for (int k = 0; k < 4; k++) {
            const int wr = i - k;
            if (wr >= 0 && wr < 5) {
#pragma unroll
                for (int j = 0; j < 5; j++) fma2(acc[k], pv[j], sw2[wr * 5 + j]);
            }
        }
    }

    const float inv = g_invSsw;
#pragma unroll
    for (int k = 0; k < 4; k++) {
        float n, dn; unpack2(acc[k], n, dn);
        float gxs = __fdividef(n, dn + EPSF);  // gx_s
        float qq  = dn * inv;                  // cgx_s
        g_pq[plane + (size_t)(h0 + r0 + k) * W + (w0 + tx)] = make_float2(qq * gxs, qq);
    }
}

// ---------------------------------------------------------------------------
// K3: 1x1 channel conv (32 -> 32). Block = 128 contiguous pixels of one batch.
// Warp-per-pixel-group, lane = output channel:
//   - pq tile staged in smem [px][c] (stride 34 u64 -> LDS.128-able)
//   - weights in registers (wr[32] u64, lane o holds column o)
//   - per pixel: 16 broadcast LDS.128 + 32 FMA2 (4 indep acc chains)
//   - results staged in smem, then coalesced stores
// ---------------------------------------------------------------------------
constexpr int K3_PIX = 128;
constexpr int K3_THREADS = 256;
constexpr int PQ_STRIDE = 34;                    // u64; even -> 16B aligned rows
constexpr int STG_STRIDE = 129;                  // floats; odd -> conflict-free lane writes

__global__ __launch_bounds__(K3_THREADS) void k3_chconv(const float* __restrict__ bias,
                                                        float* __restrict__ out) {
    __shared__ unsigned long long sPQ[K3_PIX * PQ_STRIDE];       // 34816 B
    __shared__ float stage[2 * O * STG_STRIDE];                  // 33024 B

    const int tid = threadIdx.x;
    const int lane = tid & 31;
    const int warp = tid >> 5;                   // 0..7
    const int b = blockIdx.y;
    const int pix0 = blockIdx.x * K3_PIX;

    // load pq tile: [c][px] gmem -> [px][c] smem
    const size_t base = (size_t)b * C * HW + pix0;
#pragma unroll
    for (int it = 0; it < (K3_PIX * C) / K3_THREADS; it++) {     // 16 iters
        int idx = it * K3_THREADS + tid;
        int c = idx >> 7;                        // K3_PIX = 128
        int px = idx & (K3_PIX - 1);
        float2 pq = g_pq[base + (size_t)c * HW + px];
        sPQ[px * PQ_STRIDE + c] = pack2(pq.x, pq.y);
    }

    // per-lane weight column (o = lane)
    unsigned long long wr[C];
#pragma unroll
    for (int cc = 0; cc < C; cc++) wr[cc] = g_cwT2[cc * O + lane];
    const float bs = bias[lane];
    const float invc = g_invScw;

    __syncthreads();

    // compute: warp handles pixels warp*16 .. warp*16+15
#pragma unroll
    for (int i = 0; i < K3_PIX / 8; i++) {       // 16 pixels per warp
        const int px = warp * (K3_PIX / 8) + i;
        const unsigned long long* p = sPQ + px * PQ_STRIDE;
        unsigned long long a0 = 0ULL, a1 = 0ULL, a2 = 0ULL, a3 = 0ULL;
#pragma unroll
        for (int cc = 0; cc < C; cc += 4) {
            ulonglong2 x01 = *(const ulonglong2*)(p + cc);       // broadcast LDS.128
            ulonglong2 x23 = *(const ulonglong2*)(p + cc + 2);
            fma2(a0, x01.x, wr[cc]);
            fma2(a1, x01.y, wr[cc + 1]);
            fma2(a2, x23.x, wr[cc + 2]);
            fma2(a3, x23.y, wr[cc + 3]);
        }
        float n0, d0, n1, d1, n2, d2, n3, d3;
        unpack2(a0, n0, d0); unpack2(a1, n1, d1);
        unpack2(a2, n2, d2); unpack2(a3, n3, d3);
        float n = (n0 + n1) + (n2 + n3);
        float dn = (d0 + d1) + (d2 + d3);
        stage[lane * STG_STRIDE + px]                  = __fdividef(n, dn + EPSF) + bs; // gx_out
        stage[O * STG_STRIDE + lane * STG_STRIDE + px] = dn * invc;                     // cgx_out
    }
    __syncthreads();

    // coalesced stores
    const size_t outb = (size_t)b * O * HW + pix0;
#pragma unroll
    for (int it = 0; it < (O * K3_PIX) / K3_THREADS; it++) {     // 16 iters
        int idx = it * K3_THREADS + tid;
        int o = idx >> 7;
        int px = idx & (K3_PIX - 1);
        size_t g = outb + (size_t)o * HW + px;
        out[g]        = stage[o * STG_STRIDE + px];
        out[NTOT + g] = stage[O * STG_STRIDE + o * STG_STRIDE + px];
    }
}

// ---------------------------------------------------------------------------
extern "C" void kernel_launch(void* const* d_in, const int* in_sizes, int n_in,
                              void* d_out, int out_size) {
    const float* d     = (const float*)d_in[0];
    const float* cd    = (const float*)d_in[1];
    const float* gx    = (const float*)d_in[2];
    const float* cgx   = (const float*)d_in[3];
    const float* wprop = (const float*)d_in[4];
    const float* sw    = (const float*)d_in[5];
    const float* cw    = (const float*)d_in[6];
    const float* bias  = (const float*)d_in[7];
    float* out = (float*)d_out;

    k0_weights<<<1, 256>>>(wprop, sw, cw);

    dim3 g12(64, C, B);            // 8x8 tiles of 32x32, per (c, b)
    k12_prop_dwconv<<<g12, 256>>>(d, cd, gx, cgx);

    dim3 g3(HW / K3_PIX, B);       // 512 pixel-chunks per batch
    k3_chconv<<<g3, K3_THREADS>>>(bias, out);
}

// round 10
// speedup vs baseline: 1.6508x; 1.1477x over previous
#include <cuda_runtime.h>

#define EPSF 1e-20f

constexpr int B = 8, C = 32, O = 32, H = 256, W = 256;
constexpr int HW = H * W;                         // 65536
constexpr long long NTOT = (long long)B * O * HW;

// Scratch (allocation-free rule: __device__ globals). 128 MiB.
__device__ float2 g_pq[B * C * HW];

// K0 outputs
__device__ unsigned long long g_sw2[C * 25];     // inv * softplus(spatial_weight), pair-packed
__device__ unsigned long long g_cwT2[C * O];     // softplus(channel_weight) transposed [c][o], pair-packed
__device__ float g_alpha[C];                     // wp/(1+wp)
__device__ float g_beta[C];                      // 1/(1+wp)
__device__ float g_invScw;

__device__ __forceinline__ float softplusf(float x) { return __logf(1.0f + __expf(x)); }

__device__ __forceinline__ unsigned long long pack2(float lo, float hi) {
    unsigned long long v;
    asm("mov.b64 %0, {%1, %2};" : "=l"(v) : "f"(lo), "f"(hi));
    return v;
}
__device__ __forceinline__ void unpack2(unsigned long long v, float& lo, float& hi) {
    asm("mov.b64 {%0, %1}, %2;" : "=f"(lo), "=f"(hi) : "l"(v));
}
__device__ __forceinline__ void fma2(unsigned long long& acc, unsigned long long a, unsigned long long w) {
    asm("fma.rn.f32x2 %0, %1, %2, %0;" : "+l"(acc) : "l"(a), "l"(w));
}

// ---------------------------------------------------------------------------
// K0: softplus all weights once; fold 1/sum(sw) into the depthwise weights.
// ---------------------------------------------------------------------------
__global__ void k0_weights(const float* __restrict__ wprop,
                           const float* __restrict__ sw_raw,
                           const float* __restrict__ cw_raw) {
    __shared__ float red[32];
    const int t = threadIdx.x;            // 1024 threads = 32 warps

    float s = 0.f;
    for (int i = t; i < C * 25; i += 1024) s += softplusf(sw_raw[i]);
#pragma unroll
    for (int o = 16; o; o >>= 1) s += __shfl_down_sync(~0u, s, o);
    if ((t & 31) == 0) red[t >> 5] = s;
    __syncthreads();
    if (t < 32) {
        float v = red[t];
#pragma unroll
        for (int o = 16; o; o >>= 1) v += __shfl_down_sync(~0u, v, o);
        if (t == 0) red[0] = 1.0f / v;
    }
    __syncthreads();
    const float inv = red[0];
    for (int i = t; i < C * 25; i += 1024) {
        float w = inv * softplusf(sw_raw[i]);
        g_sw2[i] = pack2(w, w);
    }
    __syncthreads();

    float s2 = 0.f;
    for (int i = t; i < O * C; i += 1024) {
        int c = i >> 5, o = i & 31;       // i = c*32 + o
        float w = softplusf(cw_raw[o * C + c]);
        g_cwT2[i] = pack2(w, w);
        s2 += w;
    }
#pragma unroll
    for (int o = 16; o; o >>= 1) s2 += __shfl_down_sync(~0u, s2, o);
    if ((t & 31) == 0) red[t >> 5] = s2;
    __syncthreads();
    if (t < 32) {
        float v = red[t];
#pragma unroll
        for (int o = 16; o; o >>= 1) v += __shfl_down_sync(~0u, v, o);
        if (t == 0) g_invScw = 1.0f / v;
    }

    if (t < C) {
        float wp = softplusf(wprop[t]);
        g_alpha[t] = wp / (1.0f + wp);
        g_beta[t]  = 1.0f / (1.0f + wp);
    }
}

// ---------------------------------------------------------------------------
// K12: simplified prop (p = alpha*cgx*gx, q = alpha*cgx + beta*cd^2*interior)
// + depthwise 5x5 conv with inv-folded weights. Pure linear, divide-free.
// One block = one (b, c, 32x32 tile). Phase A vectorized over pixel pairs.
// ---------------------------------------------------------------------------
constexpr int HST = 38;                   // halo row stride in u64 (16B-aligned pairs)

__global__ __launch_bounds__(256) void k12_prop_dwconv(
    const float* __restrict__ cd, const float* __restrict__ gx,
    const float* __restrict__ cgx) {

    __shared__ unsigned long long sPQ[36 * HST];
    __shared__ unsigned long long sw2[25];

    const int tid = threadIdx.x;
    const int b = blockIdx.z, c = blockIdx.y;
    const int h0 = (blockIdx.x >> 3) * 32;
    const int w0 = (blockIdx.x & 7) * 32;

    if (tid < 25) sw2[tid] = g_sw2[c * 25 + tid];
    const float alpha = g_alpha[c];
    const float beta  = g_beta[c];

    const size_t plane = ((size_t)b * C + c) * HW;

    // Phase A: 36 rows x 18 aligned pixel-pairs = 648 jobs
    for (int idx = tid; idx < 648; idx += 256) {
        int hh = idx / 18, pw = idx - hh * 18;
        int gh = h0 + hh - 2, gw = w0 + pw * 2 - 2;   // gw even; pair fully in or out
        unsigned long long v0 = 0ULL, v1 = 0ULL;
        if ((unsigned)gh < (unsigned)H && (unsigned)gw < (unsigned)W) {
            size_t g = plane + (size_t)gh * W + gw;
            float2 cd2 = *(const float2*)(cd + g);
            float2 gx2 = *(const float2*)(gx + g);
            float2 cg2 = *(const float2*)(cgx + g);
            float m0 = alpha * cg2.x, m1 = alpha * cg2.y;
            float cz0 = (gw == 0)         ? 0.f : cd2.x;   // left edge col
            float cz1 = (gw + 1 == W - 1) ? 0.f : cd2.y;   // right edge col
            v0 = pack2(m0 * gx2.x, fmaf(beta * cz0, cz0, m0));
            v1 = pack2(m1 * gx2.y, fmaf(beta * cz1, cz1, m1));
        }
        *(ulonglong2*)(sPQ + hh * HST + pw * 2) = make_ulonglong2(v0, v1);
    }
    __syncthreads();

    // Phase B: conv. thread (tx, ty) -> col tx, rows ty*4 .. ty*4+3
    const int tx = tid & 31, ty = tid >> 5;
    const int r0 = ty * 4;
    unsigned long long acc[4] = {0ULL, 0ULL, 0ULL, 0ULL};

#pragma unroll
    for (int i = 0; i < 8; i++) {
        unsigned long long pv[5];
#pragma unroll
        for (int j = 0; j < 5; j++) pv[j] = sPQ[(r0 + i) * HST + tx + j];
#pragma unroll
        for (int k = 0; k < 4; k++) {
            const int wr = i - k;
            if (wr >= 0 && wr < 5) {
#pragma unroll
                for (int j = 0; j < 5; j++) fma2(acc[k], pv[j], sw2[wr * 5 + j]);
            }
        }
    }

    // epilogue: (p2, q2) = (inv*nom, inv*denom) already — store directly
#pragma unroll
    for (int k = 0; k < 4; k++) {
        g_pq[plane + (size_t)(h0 + r0 + k) * W + (w0 + tx)] = *(float2*)&acc[k];
    }
}

// ---------------------------------------------------------------------------
// K3: 1x1 channel conv (32 -> 32). Block = 128 contiguous pixels of one batch.
// Warp-per-pixel-group, lane = output channel.
// ---------------------------------------------------------------------------
constexpr int K3_PIX = 128;
constexpr int K3_THREADS = 256;
constexpr int PQ_STRIDE = 34;                    // u64; even -> 16B aligned rows
constexpr int STG_STRIDE = 129;                  // floats; odd -> conflict-free lane writes

__global__ __launch_bounds__(K3_THREADS) void k3_chconv(const float* __restrict__ bias,
                                                        float* __restrict__ out) {
    __shared__ unsigned long long sPQ[K3_PIX * PQ_STRIDE];
    __shared__ float stage[2 * O * STG_STRIDE];

    const int tid = threadIdx.x;
    const int lane = tid & 31;
    const int warp = tid >> 5;
    const int b = blockIdx.y;
    const int pix0 = blockIdx.x * K3_PIX;

    // load pq tile: [c][px] gmem -> [px][c] smem
    const size_t base = (size_t)b * C * HW + pix0;
#pragma unroll
    for (int it = 0; it < (K3_PIX * C) / K3_THREADS; it++) {
        int idx = it * K3_THREADS + tid;
        int c = idx >> 7;
        int px = idx & (K3_PIX - 1);
        float2 pq = g_pq[base + (size_t)c * HW + px];
        sPQ[px * PQ_STRIDE + c] = pack2(pq.x, pq.y);
    }

    unsigned long long wr[C];
#pragma unroll
    for (int cc = 0; cc < C; cc++) wr[cc] = g_cwT2[cc * O + lane];
    const float bs = bias[lane];
    const float invc = g_invScw;

    __syncthreads();

#pragma unroll
    for (int i = 0; i < K3_PIX / 8; i++) {
        const int px = warp * (K3_PIX / 8) + i;
        const unsigned long long* p = sPQ + px * PQ_STRIDE;
        unsigned long long a0 = 0ULL, a1 = 0ULL, a2 = 0ULL, a3 = 0ULL;
#pragma unroll
        for (int cc = 0; cc < C; cc += 4) {
            ulonglong2 x01 = *(const ulonglong2*)(p + cc);
            ulonglong2 x23 = *(const ulonglong2*)(p + cc + 2);
            fma2(a0, x01.x, wr[cc]);
            fma2(a1, x01.y, wr[cc + 1]);
            fma2(a2, x23.x, wr[cc + 2]);
            fma2(a3, x23.y, wr[cc + 3]);
        }
        float n0, d0, n1, d1, n2, d2, n3, d3;
        unpack2(a0, n0, d0); unpack2(a1, n1, d1);
        unpack2(a2, n2, d2); unpack2(a3, n3, d3);
        float n = (n0 + n1) + (n2 + n3);
        float dn = (d0 + d1) + (d2 + d3);
        stage[lane * STG_STRIDE + px]                  = __fdividef(n, dn + EPSF) + bs; // gx_out
        stage[O * STG_STRIDE + lane * STG_STRIDE + px] = dn * invc;                     // cgx_out
    }
    __syncthreads();

    const size_t outb = (size_t)b * O * HW + pix0;
#pragma unroll
    for (int it = 0; it < (O * K3_PIX) / K3_THREADS; it++) {
        int idx = it * K3_THREADS + tid;
        int o = idx >> 7;
        int px = idx & (K3_PIX - 1);
        size_t g = outb + (size_t)o * HW + px;
        out[g]        = stage[o * STG_STRIDE + px];
        out[NTOT + g] = stage[O * STG_STRIDE + o * STG_STRIDE + px];
    }
}

// ---------------------------------------------------------------------------
extern "C" void kernel_launch(void* const* d_in, const int* in_sizes, int n_in,
                              void* d_out, int out_size) {
    const float* cd    = (const float*)d_in[1];
    const float* gx    = (const float*)d_in[2];
    const float* cgx   = (const float*)d_in[3];
    const float* wprop = (const float*)d_in[4];
    const float* sw    = (const float*)d_in[5];
    const float* cw    = (const float*)d_in[6];
    const float* bias  = (const float*)d_in[7];
    float* out = (float*)d_out;

    k0_weights<<<1, 1024>>>(wprop, sw, cw);

    dim3 g12(64, C, B);            // 8x8 tiles of 32x32, per (c, b)
    k12_prop_dwconv<<<g12, 256>>>(cd, gx, cgx);

    dim3 g3(HW / K3_PIX, B);       // 512 pixel-chunks per batch
    k3_chconv<<<g3, K3_THREADS>>>(bias, out);
}